// round 9
// baseline (speedup 1.0000x reference)
#include <cuda_runtime.h>
#include <cuda_bf16.h>
#include <cstdint>

// MyConv2D via implicit GEMM on warp-level mma.sync (bf16 hi/lo 3-pass).
// R7: fragment double-buffering — all ldmatrix for k-step ks+1 are issued
//     before the 48 MMAs of step ks (asm volatile keeps source order), so
//     LDSM latency hides under the MMA stream. B-lo gets dedicated regs.
//
// x:[64,64,64,64]f32  w:[128,64,3,3]f32  bias:[128]f32 -> out:[64,128,62,62]f32
// CTA: M=128 co x N=128 px (2 out rows x 64 cols), K = 9 taps x 64 ci.
// Split v = hi + lo (bf16): D += Ah*Bh + Al*Bh + Ah*Bl  (~5e-6 rel err).

namespace {

constexpr int CIn = 64, COut = 128, H = 64, W = 64, OH = 62, OW = 62;
constexpr int BATCH = 64;
constexpr int THREADS = 256;
constexpr int TILES_PER_B = 31;            // 31 x 2 out rows = 62

// ---- smem byte offsets (dynamic) ----
constexpr int SM_A0    = 0;                // tap buf 0: hi @+0, lo @+16384
constexpr int SM_A1    = 32768;            // tap buf 1
constexpr int SM_B_HI  = 65536;            // 264 px x 64 ci bf16 SW128 = 33792 B
constexpr int SM_B_LO  = 99328;
constexpr int SM_X     = 133120;           // 64 ci x 136 fp32 staging
constexpr int SM_TOTAL = 167936;
constexpr int B_LO_DELTA = SM_B_LO - SM_B_HI;   // 33792

__device__ __align__(16) __nv_bfloat16 g_whi[9 * 128 * 64];
__device__ __align__(16) __nv_bfloat16 g_wlo[9 * 128 * 64];

__device__ __forceinline__ uint32_t smem_u32(const void* p) {
    uint32_t a;
    asm("{ .reg .u64 t; cvta.to.shared.u64 t, %1; cvt.u32.u64 %0, t; }"
        : "=r"(a) : "l"(p));
    return a;
}
__device__ __forceinline__ uint32_t sw128(uint32_t off) {
    return off ^ ((off >> 3) & 0x70);
}
__device__ __forceinline__ uint64_t to_global(const void* p) {
    uint64_t g;
    asm("cvta.to.global.u64 %0, %1;" : "=l"(g) : "l"(p));
    return g;
}

#define STS128(r0, r1, r2, r3, a) \
    asm volatile("st.shared.v4.b32 [%0], {%1, %2, %3, %4};" \
                 :: "r"(a), "r"(r0), "r"(r1), "r"(r2), "r"(r3) : "memory")
#define STS128F(f0, f1, f2, f3, a) \
    asm volatile("st.shared.v4.f32 [%0], {%1, %2, %3, %4};" \
                 :: "r"(a), "f"(f0), "f"(f1), "f"(f2), "f"(f3) : "memory")
#define CP_ASYNC16(dst, src) \
    asm volatile("cp.async.cg.shared.global [%0], [%1], 16;" \
                 :: "r"(dst), "l"(src) : "memory")
#define CP_COMMIT() asm volatile("cp.async.commit_group;" ::: "memory")
#define CP_WAIT0()  asm volatile("cp.async.wait_group 0;" ::: "memory")

__device__ __forceinline__ void ldm_x4(uint32_t& r0, uint32_t& r1,
                                       uint32_t& r2, uint32_t& r3, uint32_t a) {
    asm volatile("ldmatrix.sync.aligned.m8n8.x4.shared.b16 {%0,%1,%2,%3}, [%4];"
                 : "=r"(r0), "=r"(r1), "=r"(r2), "=r"(r3) : "r"(a));
}
__device__ __forceinline__ void mma_bf16(float* c, const uint32_t* a,
                                         const uint32_t* b) {
    asm volatile(
        "mma.sync.aligned.m16n8k16.row.col.f32.bf16.bf16.f32 "
        "{%0,%1,%2,%3}, {%4,%5,%6,%7}, {%8,%9}, {%0,%1,%2,%3};"
        : "+f"(c[0]), "+f"(c[1]), "+f"(c[2]), "+f"(c[3])
        : "r"(a[0]), "r"(a[1]), "r"(a[2]), "r"(a[3]), "r"(b[0]), "r"(b[1]));
}

// fragment set for one k16 step (double-buffered across ks)
struct Frags {
    uint32_t bh[16], bl[16], ah[8], al[8];
};

// issue all 12 ldmatrix.x4 for one k-step (kept in source order vs mma)
__device__ __forceinline__ void load_frags(Frags& f, uint32_t ab, uint32_t b_base,
                                           uint32_t a_rb0, uint32_t aoff,
                                           uint32_t boff) {
    #pragma unroll
    for (int i2 = 0; i2 < 4; ++i2)
        ldm_x4(f.bh[i2 * 4 + 0], f.bh[i2 * 4 + 1], f.bh[i2 * 4 + 2], f.bh[i2 * 4 + 3],
               b_base + (uint32_t)(i2 * 2048) + boff);
    #pragma unroll
    for (int m = 0; m < 2; ++m)
        ldm_x4(f.ah[m * 4 + 0], f.ah[m * 4 + 1], f.ah[m * 4 + 2], f.ah[m * 4 + 3],
               ab + a_rb0 + (uint32_t)(m * 2048) + aoff);
    #pragma unroll
    for (int m = 0; m < 2; ++m)
        ldm_x4(f.al[m * 4 + 0], f.al[m * 4 + 1], f.al[m * 4 + 2], f.al[m * 4 + 3],
               ab + 16384 + a_rb0 + (uint32_t)(m * 2048) + aoff);
    #pragma unroll
    for (int i2 = 0; i2 < 4; ++i2)
        ldm_x4(f.bl[i2 * 4 + 0], f.bl[i2 * 4 + 1], f.bl[i2 * 4 + 2], f.bl[i2 * 4 + 3],
               b_base + B_LO_DELTA + (uint32_t)(i2 * 2048) + boff);
}

// ---- weight preconvert: w[co][ci][kk] -> g_w{hi,lo}[kk][co][ci] ----
__global__ void wsplit_kernel(const float* __restrict__ w) {
    int i = blockIdx.x * blockDim.x + threadIdx.x;
    if (i >= 9 * 128 * 64) return;
    int ci = i & 63;
    int co = (i >> 6) & 127;
    int kk = i >> 13;
    float v = w[(co * CIn + ci) * 9 + kk];
    __nv_bfloat16 h = __float2bfloat16(v);
    g_whi[i] = h;
    g_wlo[i] = __float2bfloat16(v - __bfloat162float(h));
}

__device__ __forceinline__ void prefetch_A(int kk, uint32_t dst, int tid) {
    const uint64_t whk = to_global(g_whi) + (uint64_t)kk * 8192 * 2;
    const uint64_t wlk = to_global(g_wlo) + (uint64_t)kk * 8192 * 2;
    #pragma unroll
    for (int it = 0; it < 4; ++it) {
        int i   = tid + it * THREADS;
        int co  = i & 127;
        int grp = i >> 7;
        uint32_t sw   = sw128((uint32_t)(co * 128 + grp * 16));
        uint64_t soff = (uint64_t)(co * 64 + grp * 8) * 2;
        CP_ASYNC16(dst + sw,         whk + soff);
        CP_ASYNC16(dst + 16384 + sw, wlk + soff);
    }
}

// ---- main kernel ----
__global__ __launch_bounds__(THREADS, 1)
void conv_mma_kernel(const float* __restrict__ x,
                     const float* __restrict__ bias,
                     float* __restrict__ out) {
    extern __shared__ __align__(1024) char smem[];
    const uint32_t sb  = smem_u32(smem);
    const int tid = threadIdx.x, wid = tid >> 5, lid = tid & 31;
    const int b   = blockIdx.x / TILES_PER_B;
    const int t   = blockIdx.x - b * TILES_PER_B;
    const int oy0 = t * 2;

    const int wm = wid & 3;        // M group: co rows [wm*32, +32)
    const int wn = wid >> 2;       // N group: output row wn (0/1)

    const uint32_t a_xm   = (uint32_t)(lid & 7) << 4;
    const uint32_t a_rb0  = (uint32_t)(wm * 32 + (lid & 15)) * 128;
    const uint32_t a_kadd = (uint32_t)(lid >> 4) * 16;
    const uint32_t b_kadd = (uint32_t)((lid >> 3) & 1) * 16;

    float acc[2][8][4];
    #pragma unroll
    for (int m = 0; m < 2; ++m)
        #pragma unroll
        for (int n = 0; n < 8; ++n)
            #pragma unroll
            for (int q = 0; q < 4; ++q)
                acc[m][n][q] = 0.0f;

    const float* xb = x + (size_t)b * CIn * H * W;
    float* s_x = reinterpret_cast<float*>(smem + SM_X);

    prefetch_A(0, sb + SM_A0, tid);
    CP_COMMIT();

    // ============ one-time B staging: 4 halo rows x 66 cols x 64 ci ============
    #pragma unroll 1
    for (int c2 = 0; c2 < 2; ++c2) {
        #pragma unroll
        for (int it = 0; it < 8; ++it) {
            int i    = tid + it * THREADS;
            int qcol = i & 15;
            int lr   = (i >> 4) & 1;
            int ci   = i >> 5;
            int gy   = oy0 + c2 * 2 + lr;
            const float4 v = *reinterpret_cast<const float4*>(
                xb + ((size_t)ci * H + gy) * W + qcol * 4);
            STS128F(v.x, v.y, v.z, v.w,
                    sb + SM_X + (uint32_t)(ci * 136 + lr * 68 + qcol * 4) * 4);
        }
        {
            int ci = tid & 63, lr = (tid >> 6) & 1, cz = 64 + (tid >> 7);
            s_x[ci * 136 + lr * 68 + cz] = 0.0f;
        }
        __syncthreads();

        #pragma unroll
        for (int it = 0; it < 5; ++it) {
            int i = tid + it * THREADS;
            if (i < 1056) {
                int pix = i % 132;
                int grp = i / 132;
                int lr  = (pix >= 66);
                int lc  = pix + 2 * lr;
                uint32_t hp[4], lp[4];
                #pragma unroll
                for (int j = 0; j < 4; ++j) {
                    float v0 = s_x[((grp << 3) + 2 * j)     * 136 + lc];
                    float v1 = s_x[((grp << 3) + 2 * j + 1) * 136 + lc];
                    __nv_bfloat16 h0 = __float2bfloat16(v0);
                    __nv_bfloat16 h1 = __float2bfloat16(v1);
                    __nv_bfloat16 l0 = __float2bfloat16(v0 - __bfloat162float(h0));
                    __nv_bfloat16 l1 = __float2bfloat16(v1 - __bfloat162float(h1));
                    hp[j] = (uint32_t)__bfloat16_as_ushort(h0) |
                            ((uint32_t)__bfloat16_as_ushort(h1) << 16);
                    lp[j] = (uint32_t)__bfloat16_as_ushort(l0) |
                            ((uint32_t)__bfloat16_as_ushort(l1) << 16);
                }
                uint32_t fpix = (uint32_t)(c2 * 132 + pix);
                uint32_t adr  = fpix * 128 +
                                (((uint32_t)grp * 16) ^ ((fpix & 7) << 4));
                STS128(hp[0], hp[1], hp[2], hp[3], sb + SM_B_HI + adr);
                STS128(lp[0], lp[1], lp[2], lp[3], sb + SM_B_LO + adr);
            }
        }
        __syncthreads();
    }

    // ============ main loop: 9 taps, A double-buffered, frags pipelined ============
    Frags fr[2];
    #pragma unroll 1
    for (int kk = 0; kk < 9; ++kk) {
        CP_WAIT0();
        __syncthreads();
        if (kk < 8) {
            prefetch_A(kk + 1, sb + ((kk + 1) & 1 ? SM_A1 : SM_A0), tid);
            CP_COMMIT();
        }

        const uint32_t ab = sb + ((kk & 1) ? SM_A1 : SM_A0);
        const int ky = kk / 3, kx = kk - 3 * ky;
        const uint32_t lanepix =
            (uint32_t)((wn + ky) * 66 + kx + ((lid >> 4) & 1) * 8 + (lid & 7));
        const uint32_t b_base = sb + SM_B_HI + lanepix * 128;
        const uint32_t b_xm2  = (lanepix & 7) << 4;

        // preload ks=0 fragments
        load_frags(fr[0], ab, b_base, a_rb0, a_kadd ^ a_xm, b_kadd ^ b_xm2);

        #pragma unroll
        for (int ks = 0; ks < 4; ++ks) {
            // issue next step's loads BEFORE current step's mma (pipelining)
            if (ks < 3) {
                const uint32_t aoff = ((uint32_t)((ks + 1) * 32) + a_kadd) ^ a_xm;
                const uint32_t boff = ((uint32_t)((ks + 1) * 32) + b_kadd) ^ b_xm2;
                load_frags(fr[(ks + 1) & 1], ab, b_base, a_rb0, aoff, boff);
            }
            Frags& f = fr[ks & 1];
            #pragma unroll
            for (int m = 0; m < 2; ++m)         // HH
                #pragma unroll
                for (int n = 0; n < 8; ++n)
                    mma_bf16(acc[m][n], f.ah + m * 4, f.bh + (n >> 1) * 4 + (n & 1) * 2);
            #pragma unroll
            for (int m = 0; m < 2; ++m)         // LH
                #pragma unroll
                for (int n = 0; n < 8; ++n)
                    mma_bf16(acc[m][n], f.al + m * 4, f.bh + (n >> 1) * 4 + (n & 1) * 2);
            #pragma unroll
            for (int m = 0; m < 2; ++m)         // HL
                #pragma unroll
                for (int n = 0; n < 8; ++n)
                    mma_bf16(acc[m][n], f.ah + m * 4, f.bl + (n >> 1) * 4 + (n & 1) * 2);
        }
    }

    // ============ epilogue: bias + store ============
    const int oy = oy0 + wn;
    #pragma unroll
    for (int m = 0; m < 2; ++m) {
        const int co0 = wm * 32 + m * 16 + (lid >> 2);
        const float bv0 = __ldg(&bias[co0]);
        const float bv1 = __ldg(&bias[co0 + 8]);
        float* op0 = out + ((size_t)(b * COut + co0)     * OH + oy) * OW;
        float* op1 = out + ((size_t)(b * COut + co0 + 8) * OH + oy) * OW;
        #pragma unroll
        for (int n = 0; n < 8; ++n) {
            const int col = n * 8 + (lid & 3) * 2;
            if (col < OW) {
                float2 v0 = make_float2(acc[m][n][0] + bv0, acc[m][n][1] + bv0);
                float2 v1 = make_float2(acc[m][n][2] + bv1, acc[m][n][3] + bv1);
                *reinterpret_cast<float2*>(op0 + col) = v0;
                *reinterpret_cast<float2*>(op1 + col) = v1;
            }
        }
    }
}

} // namespace

extern "C" void kernel_launch(void* const* d_in, const int* in_sizes, int n_in,
                              void* d_out, int out_size) {
    const float* x    = nullptr;
    const float* wgt  = nullptr;
    const float* bias = nullptr;
    for (int i = 0; i < n_in; ++i) {
        const int sz = in_sizes[i];
        if (sz == BATCH * CIn * H * W) x    = (const float*)d_in[i];
        else if (sz == COut * CIn * 9) wgt  = (const float*)d_in[i];
        else if (sz == COut)           bias = (const float*)d_in[i];
    }
    if (!x)    x    = (const float*)d_in[0];
    if (!wgt)  wgt  = (const float*)d_in[1];
    if (!bias) bias = (const float*)d_in[2];
    float* out = (float*)d_out;
    (void)out_size;

    cudaFuncSetAttribute(conv_mma_kernel,
                         cudaFuncAttributeMaxDynamicSharedMemorySize, SM_TOTAL);

    wsplit_kernel<<<(9 * 128 * 64 + 255) / 256, 256>>>(wgt);
    conv_mma_kernel<<<BATCH * TILES_PER_B, THREADS, SM_TOTAL>>>(x, bias, out);
}

// round 10
// speedup vs baseline: 1.0671x; 1.0671x over previous
#include <cuda_runtime.h>
#include <cuda_bf16.h>
#include <cstdint>

// MyConv2D via implicit GEMM on warp-level mma.sync (bf16 hi/lo 3-pass).
// R9: 384 threads (3 warps/SMSP), CTA tile N=192 px (3 out rows x 64 cols).
//     Per-warp work unchanged; staging/barrier costs amortized over 1.5x
//     compute; waves 13.4 -> 9.1. Compute body = simple in-order (R6 form).
//
// x:[64,64,64,64]f32  w:[128,64,3,3]f32  bias:[128]f32 -> out:[64,128,62,62]f32
// CTA: M=128 co x N=192 px, K = 9 taps x 64 ci.
// Split v = hi + lo (bf16): D += Ah*Bh + Al*Bh + Ah*Bl  (~5e-6 rel err).

namespace {

constexpr int CIn = 64, COut = 128, H = 64, W = 64, OH = 62, OW = 62;
constexpr int BATCH = 64;
constexpr int THREADS = 384;               // 12 warps, 3 per SMSP
constexpr int TILES_PER_B = 21;            // 21 x 3 out rows = 63 (row 62 pad)

// ---- smem byte offsets (dynamic) ----
constexpr int SM_A0    = 0;                // tap buf 0: hi @+0, lo @+16384
constexpr int SM_A1    = 32768;            // tap buf 1
constexpr int SM_B_HI  = 65536;            // 330 px x 64 ci bf16 SW128 = 42240 B
constexpr int SM_B_LO  = 107776;           // 42240 B
constexpr int SM_X     = 150016;           // 64 ci x 136 fp32 staging = 34816 B
constexpr int SM_TOTAL = 184832;           // 180.5 KB
constexpr int B_LO_DELTA = SM_B_LO - SM_B_HI;   // 42240

__device__ __align__(16) __nv_bfloat16 g_whi[9 * 128 * 64];
__device__ __align__(16) __nv_bfloat16 g_wlo[9 * 128 * 64];

__device__ __forceinline__ uint32_t smem_u32(const void* p) {
    uint32_t a;
    asm("{ .reg .u64 t; cvta.to.shared.u64 t, %1; cvt.u32.u64 %0, t; }"
        : "=r"(a) : "l"(p));
    return a;
}
__device__ __forceinline__ uint32_t sw128(uint32_t off) {
    return off ^ ((off >> 3) & 0x70);
}
__device__ __forceinline__ uint64_t to_global(const void* p) {
    uint64_t g;
    asm("cvta.to.global.u64 %0, %1;" : "=l"(g) : "l"(p));
    return g;
}

#define STS128(r0, r1, r2, r3, a) \
    asm volatile("st.shared.v4.b32 [%0], {%1, %2, %3, %4};" \
                 :: "r"(a), "r"(r0), "r"(r1), "r"(r2), "r"(r3) : "memory")
#define STS128F(f0, f1, f2, f3, a) \
    asm volatile("st.shared.v4.f32 [%0], {%1, %2, %3, %4};" \
                 :: "r"(a), "f"(f0), "f"(f1), "f"(f2), "f"(f3) : "memory")
#define CP_ASYNC16(dst, src) \
    asm volatile("cp.async.cg.shared.global [%0], [%1], 16;" \
                 :: "r"(dst), "l"(src) : "memory")
#define CP_COMMIT() asm volatile("cp.async.commit_group;" ::: "memory")
#define CP_WAIT0()  asm volatile("cp.async.wait_group 0;" ::: "memory")

__device__ __forceinline__ void ldm_x4(uint32_t& r0, uint32_t& r1,
                                       uint32_t& r2, uint32_t& r3, uint32_t a) {
    asm volatile("ldmatrix.sync.aligned.m8n8.x4.shared.b16 {%0,%1,%2,%3}, [%4];"
                 : "=r"(r0), "=r"(r1), "=r"(r2), "=r"(r3) : "r"(a));
}
__device__ __forceinline__ void mma_bf16(float* c, const uint32_t* a,
                                         const uint32_t* b) {
    asm volatile(
        "mma.sync.aligned.m16n8k16.row.col.f32.bf16.bf16.f32 "
        "{%0,%1,%2,%3}, {%4,%5,%6,%7}, {%8,%9}, {%0,%1,%2,%3};"
        : "+f"(c[0]), "+f"(c[1]), "+f"(c[2]), "+f"(c[3])
        : "r"(a[0]), "r"(a[1]), "r"(a[2]), "r"(a[3]), "r"(b[0]), "r"(b[1]));
}

// ---- weight preconvert: w[co][ci][kk] -> g_w{hi,lo}[kk][co][ci] ----
__global__ void wsplit_kernel(const float* __restrict__ w) {
    int i = blockIdx.x * blockDim.x + threadIdx.x;
    if (i >= 9 * 128 * 64) return;
    int ci = i & 63;
    int co = (i >> 6) & 127;
    int kk = i >> 13;
    float v = w[(co * CIn + ci) * 9 + kk];
    __nv_bfloat16 h = __float2bfloat16(v);
    g_whi[i] = h;
    g_wlo[i] = __float2bfloat16(v - __bfloat162float(h));
}

__device__ __forceinline__ void prefetch_A(int kk, uint32_t dst, int tid) {
    const uint64_t whk = to_global(g_whi) + (uint64_t)kk * 8192 * 2;
    const uint64_t wlk = to_global(g_wlo) + (uint64_t)kk * 8192 * 2;
    #pragma unroll
    for (int it = 0; it < 3; ++it) {
        int i = tid + it * THREADS;          // 0..1151, need < 1024
        if (i < 1024) {
            int co  = i & 127;
            int grp = i >> 7;
            uint32_t sw   = sw128((uint32_t)(co * 128 + grp * 16));
            uint64_t soff = (uint64_t)(co * 64 + grp * 8) * 2;
            CP_ASYNC16(dst + sw,         whk + soff);
            CP_ASYNC16(dst + 16384 + sw, wlk + soff);
        }
    }
}

// ---- main kernel ----
__global__ __launch_bounds__(THREADS, 1)
void conv_mma_kernel(const float* __restrict__ x,
                     const float* __restrict__ bias,
                     float* __restrict__ out) {
    extern __shared__ __align__(1024) char smem[];
    const uint32_t sb  = smem_u32(smem);
    const int tid = threadIdx.x, wid = tid >> 5, lid = tid & 31;
    const int b   = blockIdx.x / TILES_PER_B;
    const int t   = blockIdx.x - b * TILES_PER_B;
    const int oy0 = t * 3;

    const int wm = wid & 3;        // M group: co rows [wm*32, +32)
    const int wn = wid >> 2;       // N group: output row wn (0,1,2)

    const uint32_t a_xm   = (uint32_t)(lid & 7) << 4;
    const uint32_t a_rb0  = (uint32_t)(wm * 32 + (lid & 15)) * 128;
    const uint32_t a_kadd = (uint32_t)(lid >> 4) * 16;
    const uint32_t b_kadd = (uint32_t)((lid >> 3) & 1) * 16;

    float acc[2][8][4];
    #pragma unroll
    for (int m = 0; m < 2; ++m)
        #pragma unroll
        for (int n = 0; n < 8; ++n)
            #pragma unroll
            for (int q = 0; q < 4; ++q)
                acc[m][n][q] = 0.0f;

    const float* xb = x + (size_t)b * CIn * H * W;
    float* s_x = reinterpret_cast<float*>(smem + SM_X);

    prefetch_A(0, sb + SM_A0, tid);
    CP_COMMIT();

    // ===== one-time B staging: 5 halo rows x 66 cols x 64 ci (3 chunks) =====
    #pragma unroll 1
    for (int c2 = 0; c2 < 3; ++c2) {
        const int nr  = (c2 == 2) ? 1 : 2;       // rows in this chunk
        const int r0  = c2 * 2;

        // gather fp32, coalesced float4 -> s_x[ci][lr*68 + col]
        const int gitems = nr * 64 * 16;         // float4 slots
        #pragma unroll 1
        for (int i = tid; i < gitems; i += THREADS) {
            int qcol = i & 15;
            int lr   = (nr == 2) ? ((i >> 4) & 1) : 0;
            int ci   = (nr == 2) ? (i >> 5) : (i >> 4);
            int gy   = oy0 + r0 + lr;
            if (gy > H - 1) gy = H - 1;          // last-tile clamp (padded rows)
            const float4 v = *reinterpret_cast<const float4*>(
                xb + ((size_t)ci * H + gy) * W + qcol * 4);
            STS128F(v.x, v.y, v.z, v.w,
                    sb + SM_X + (uint32_t)(ci * 136 + lr * 68 + qcol * 4) * 4);
        }
        // zero halo cols 64,65
        if (tid < nr * 128) {
            int ci = tid & 63;
            int lr = (nr == 2) ? ((tid >> 6) & 1) : 0;
            int cz = 64 + ((nr == 2) ? (tid >> 7) : (tid >> 6));
            s_x[ci * 136 + lr * 68 + cz] = 0.0f;
        }
        __syncthreads();

        // convert + transpose -> B hi/lo tiles [fpix][ci] SW128
        const int npx    = nr * 66;
        const int citems = npx * 8;
        #pragma unroll 1
        for (int i = tid; i < citems; i += THREADS) {
            int pix = i % npx;
            int grp = i / npx;
            int lr  = (pix >= 66);
            int lc  = pix + 2 * lr;
            uint32_t hp[4], lp[4];
            #pragma unroll
            for (int j = 0; j < 4; ++j) {
                float v0 = s_x[((grp << 3) + 2 * j)     * 136 + lc];
                float v1 = s_x[((grp << 3) + 2 * j + 1) * 136 + lc];
                __nv_bfloat16 h0 = __float2bfloat16(v0);
                __nv_bfloat16 h1 = __float2bfloat16(v1);
                __nv_bfloat16 l0 = __float2bfloat16(v0 - __bfloat162float(h0));
                __nv_bfloat16 l1 = __float2bfloat16(v1 - __bfloat162float(h1));
                hp[j] = (uint32_t)__bfloat16_as_ushort(h0) |
                        ((uint32_t)__bfloat16_as_ushort(h1) << 16);
                lp[j] = (uint32_t)__bfloat16_as_ushort(l0) |
                        ((uint32_t)__bfloat16_as_ushort(l1) << 16);
            }
            uint32_t fpix = (uint32_t)(c2 * 132 + pix);
            uint32_t adr  = fpix * 128 +
                            (((uint32_t)grp * 16) ^ ((fpix & 7) << 4));
            STS128(hp[0], hp[1], hp[2], hp[3], sb + SM_B_HI + adr);
            STS128(lp[0], lp[1], lp[2], lp[3], sb + SM_B_LO + adr);
        }
        __syncthreads();
    }

    // ===== main loop: 9 taps, A double-buffered via cp.async =====
    #pragma unroll 1
    for (int kk = 0; kk < 9; ++kk) {
        CP_WAIT0();
        __syncthreads();
        if (kk < 8) {
            prefetch_A(kk + 1, sb + ((kk + 1) & 1 ? SM_A1 : SM_A0), tid);
            CP_COMMIT();
        }

        const uint32_t ab = sb + ((kk & 1) ? SM_A1 : SM_A0);
        const int ky = kk / 3, kx = kk - 3 * ky;
        const uint32_t lanepix =
            (uint32_t)((wn + ky) * 66 + kx + ((lid >> 4) & 1) * 8 + (lid & 7));
        const uint32_t b_base = sb + SM_B_HI + lanepix * 128;
        const uint32_t b_xm2  = (lanepix & 7) << 4;

        #pragma unroll
        for (int ks = 0; ks < 4; ++ks) {
            const uint32_t aoff = ((uint32_t)(ks * 32) + a_kadd) ^ a_xm;
            const uint32_t boff = ((uint32_t)(ks * 32) + b_kadd) ^ b_xm2;

            uint32_t bh[16], ah[8], al[8];
            #pragma unroll
            for (int i2 = 0; i2 < 4; ++i2)
                ldm_x4(bh[i2 * 4 + 0], bh[i2 * 4 + 1], bh[i2 * 4 + 2], bh[i2 * 4 + 3],
                       b_base + (uint32_t)(i2 * 2048) + boff);
            #pragma unroll
            for (int m = 0; m < 2; ++m)
                ldm_x4(ah[m * 4 + 0], ah[m * 4 + 1], ah[m * 4 + 2], ah[m * 4 + 3],
                       ab + a_rb0 + (uint32_t)(m * 2048) + aoff);
            #pragma unroll
            for (int m = 0; m < 2; ++m)         // HH
                #pragma unroll
                for (int n = 0; n < 8; ++n)
                    mma_bf16(acc[m][n], ah + m * 4, bh + (n >> 1) * 4 + (n & 1) * 2);
            #pragma unroll
            for (int m = 0; m < 2; ++m)
                ldm_x4(al[m * 4 + 0], al[m * 4 + 1], al[m * 4 + 2], al[m * 4 + 3],
                       ab + 16384 + a_rb0 + (uint32_t)(m * 2048) + aoff);
            #pragma unroll
            for (int m = 0; m < 2; ++m)         // LH
                #pragma unroll
                for (int n = 0; n < 8; ++n)
                    mma_bf16(acc[m][n], al + m * 4, bh + (n >> 1) * 4 + (n & 1) * 2);
            #pragma unroll
            for (int i2 = 0; i2 < 4; ++i2)      // B-lo reuses bh regs
                ldm_x4(bh[i2 * 4 + 0], bh[i2 * 4 + 1], bh[i2 * 4 + 2], bh[i2 * 4 + 3],
                       b_base + B_LO_DELTA + (uint32_t)(i2 * 2048) + boff);
            #pragma unroll
            for (int m = 0; m < 2; ++m)         // HL
                #pragma unroll
                for (int n = 0; n < 8; ++n)
                    mma_bf16(acc[m][n], ah + m * 4, bh + (n >> 1) * 4 + (n & 1) * 2);
        }
    }

    // ===== epilogue: bias + store (row 62 of last tile skipped) =====
    const int oy = oy0 + wn;
    if (oy < OH) {
        #pragma unroll
        for (int m = 0; m < 2; ++m) {
            const int co0 = wm * 32 + m * 16 + (lid >> 2);
            const float bv0 = __ldg(&bias[co0]);
            const float bv1 = __ldg(&bias[co0 + 8]);
            float* op0 = out + ((size_t)(b * COut + co0)     * OH + oy) * OW;
            float* op1 = out + ((size_t)(b * COut + co0 + 8) * OH + oy) * OW;
            #pragma unroll
            for (int n = 0; n < 8; ++n) {
                const int col = n * 8 + (lid & 3) * 2;
                if (col < OW) {
                    float2 v0 = make_float2(acc[m][n][0] + bv0, acc[m][n][1] + bv0);
                    float2 v1 = make_float2(acc[m][n][2] + bv1, acc[m][n][3] + bv1);
                    *reinterpret_cast<float2*>(op0 + col) = v0;
                    *reinterpret_cast<float2*>(op1 + col) = v1;
                }
            }
        }
    }
}

} // namespace

extern "C" void kernel_launch(void* const* d_in, const int* in_sizes, int n_in,
                              void* d_out, int out_size) {
    const float* x    = nullptr;
    const float* wgt  = nullptr;
    const float* bias = nullptr;
    for (int i = 0; i < n_in; ++i) {
        const int sz = in_sizes[i];
        if (sz == BATCH * CIn * H * W) x    = (const float*)d_in[i];
        else if (sz == COut * CIn * 9) wgt  = (const float*)d_in[i];
        else if (sz == COut)           bias = (const float*)d_in[i];
    }
    if (!x)    x    = (const float*)d_in[0];
    if (!wgt)  wgt  = (const float*)d_in[1];
    if (!bias) bias = (const float*)d_in[2];
    float* out = (float*)d_out;
    (void)out_size;

    cudaFuncSetAttribute(conv_mma_kernel,
                         cudaFuncAttributeMaxDynamicSharedMemorySize, SM_TOTAL);

    wsplit_kernel<<<(9 * 128 * 64 + 255) / 256, 256>>>(wgt);
    conv_mma_kernel<<<BATCH * TILES_PER_B, THREADS, SM_TOTAL>>>(x, bias, out);
}

// round 14
// speedup vs baseline: 1.8005x; 1.6874x over previous
#include <cuda_runtime.h>
#include <cuda_fp16.h>
#include <cstdint>

// MyConv2D via implicit GEMM on warp-level mma.sync — R11: resubmit of R10
// (fp16 single-pass); previous round hit a pure infra failure (container
// acquisition), kernel never ran.
//
// Calibrated precision model (from measured bf16-3pass rel_err 4.86e-6 vs
// predicted 4.4e-6): fp16 single-pass -> rel_err ~2.8e-4 < 1e-3 gate.
// 3x fewer mma than the hi/lo 3-pass, 2.7x fewer ldmatrix, half the staging.
//
// x:[64,64,64,64]f32  w:[128,64,3,3]f32  bias:[128]f32 -> out:[64,128,62,62]f32
// CTA: M=128 co x N=192 px (3 out rows x 64 cols), K = 9 taps x 64 ci.
// 384 threads (12 warps, 3/SMSP). Warp tile 32co x 64px.

namespace {

constexpr int CIn = 64, COut = 128, H = 64, W = 64, OH = 62, OW = 62;
constexpr int BATCH = 64;
constexpr int THREADS = 384;
constexpr int TILES_PER_B = 21;            // 21 x 3 out rows = 63 (row 62 pad)

// ---- smem byte offsets (dynamic) ----
constexpr int SM_A0    = 0;                // tap A buf 0: 128co x 64k fp16 SW128
constexpr int SM_A1    = 16384;            // tap A buf 1
constexpr int SM_B     = 32768;            // 330 px x 64 ci fp16 SW128 = 42240 B
constexpr int SM_X     = 75008;            // 64 ci x 136 fp32 staging = 34816 B
constexpr int SM_TOTAL = 109824;           // 107.25 KB

__device__ __align__(16) __half g_wh[9 * 128 * 64];   // [kk][co][ci] fp16

__device__ __forceinline__ uint32_t smem_u32(const void* p) {
    uint32_t a;
    asm("{ .reg .u64 t; cvta.to.shared.u64 t, %1; cvt.u32.u64 %0, t; }"
        : "=r"(a) : "l"(p));
    return a;
}
__device__ __forceinline__ uint32_t sw128(uint32_t off) {
    return off ^ ((off >> 3) & 0x70);
}
__device__ __forceinline__ uint64_t to_global(const void* p) {
    uint64_t g;
    asm("cvta.to.global.u64 %0, %1;" : "=l"(g) : "l"(p));
    return g;
}

#define STS128(r0, r1, r2, r3, a) \
    asm volatile("st.shared.v4.b32 [%0], {%1, %2, %3, %4};" \
                 :: "r"(a), "r"(r0), "r"(r1), "r"(r2), "r"(r3) : "memory")
#define STS128F(f0, f1, f2, f3, a) \
    asm volatile("st.shared.v4.f32 [%0], {%1, %2, %3, %4};" \
                 :: "r"(a), "f"(f0), "f"(f1), "f"(f2), "f"(f3) : "memory")
#define CP_ASYNC16(dst, src) \
    asm volatile("cp.async.cg.shared.global [%0], [%1], 16;" \
                 :: "r"(dst), "l"(src) : "memory")
#define CP_COMMIT() asm volatile("cp.async.commit_group;" ::: "memory")
#define CP_WAIT0()  asm volatile("cp.async.wait_group 0;" ::: "memory")

__device__ __forceinline__ void ldm_x4(uint32_t& r0, uint32_t& r1,
                                       uint32_t& r2, uint32_t& r3, uint32_t a) {
    asm volatile("ldmatrix.sync.aligned.m8n8.x4.shared.b16 {%0,%1,%2,%3}, [%4];"
                 : "=r"(r0), "=r"(r1), "=r"(r2), "=r"(r3) : "r"(a));
}
__device__ __forceinline__ void mma_f16(float* c, const uint32_t* a,
                                        const uint32_t* b) {
    asm volatile(
        "mma.sync.aligned.m16n8k16.row.col.f32.f16.f16.f32 "
        "{%0,%1,%2,%3}, {%4,%5,%6,%7}, {%8,%9}, {%0,%1,%2,%3};"
        : "+f"(c[0]), "+f"(c[1]), "+f"(c[2]), "+f"(c[3])
        : "r"(a[0]), "r"(a[1]), "r"(a[2]), "r"(a[3]), "r"(b[0]), "r"(b[1]));
}

// ---- weight preconvert: w[co][ci][kk] -> g_wh[kk][co][ci] fp16 ----
__global__ void wconv_kernel(const float* __restrict__ w) {
    int i = blockIdx.x * blockDim.x + threadIdx.x;
    if (i >= 9 * 128 * 64) return;
    int ci = i & 63;
    int co = (i >> 6) & 127;
    int kk = i >> 13;
    g_wh[i] = __float2half_rn(w[(co * CIn + ci) * 9 + kk]);
}

__device__ __forceinline__ void prefetch_A(int kk, uint32_t dst, int tid) {
    const uint64_t whk = to_global(g_wh) + (uint64_t)kk * 8192 * 2;
    #pragma unroll
    for (int it = 0; it < 3; ++it) {
        int i = tid + it * THREADS;          // need < 1024 chunks of 16B
        if (i < 1024) {
            int co  = i & 127;
            int grp = i >> 7;                // 8-ci group
            uint32_t sw   = sw128((uint32_t)(co * 128 + grp * 16));
            uint64_t soff = (uint64_t)(co * 64 + grp * 8) * 2;
            CP_ASYNC16(dst + sw, whk + soff);
        }
    }
}

// ---- main kernel ----
__global__ __launch_bounds__(THREADS, 1)
void conv_mma_kernel(const float* __restrict__ x,
                     const float* __restrict__ bias,
                     float* __restrict__ out) {
    extern __shared__ __align__(1024) char smem[];
    const uint32_t sb  = smem_u32(smem);
    const int tid = threadIdx.x, wid = tid >> 5, lid = tid & 31;
    const int b   = blockIdx.x / TILES_PER_B;
    const int t   = blockIdx.x - b * TILES_PER_B;
    const int oy0 = t * 3;

    const int wm = wid & 3;        // M group: co rows [wm*32, +32)
    const int wn = wid >> 2;       // N group: output row wn (0,1,2)

    const uint32_t a_xm   = (uint32_t)(lid & 7) << 4;
    const uint32_t a_rb0  = (uint32_t)(wm * 32 + (lid & 15)) * 128;
    const uint32_t a_kadd = (uint32_t)(lid >> 4) * 16;
    const uint32_t b_kadd = (uint32_t)((lid >> 3) & 1) * 16;

    float acc[2][8][4];
    #pragma unroll
    for (int m = 0; m < 2; ++m)
        #pragma unroll
        for (int n = 0; n < 8; ++n)
            #pragma unroll
            for (int q = 0; q < 4; ++q)
                acc[m][n][q] = 0.0f;

    const float* xb = x + (size_t)b * CIn * H * W;
    float* s_x = reinterpret_cast<float*>(smem + SM_X);

    prefetch_A(0, sb + SM_A0, tid);
    CP_COMMIT();

    // ===== one-time B staging: 5 halo rows x 66 cols x 64 ci (3 chunks) =====
    #pragma unroll 1
    for (int c2 = 0; c2 < 3; ++c2) {
        const int nr = (c2 == 2) ? 1 : 2;
        const int r0 = c2 * 2;

        const int gitems = nr * 64 * 16;     // float4 slots
        #pragma unroll 1
        for (int i = tid; i < gitems; i += THREADS) {
            int qcol = i & 15;
            int lr   = (nr == 2) ? ((i >> 4) & 1) : 0;
            int ci   = (nr == 2) ? (i >> 5) : (i >> 4);
            int gy   = oy0 + r0 + lr;
            if (gy > H - 1) gy = H - 1;      // last-tile clamp (padded rows)
            const float4 v = *reinterpret_cast<const float4*>(
                xb + ((size_t)ci * H + gy) * W + qcol * 4);
            STS128F(v.x, v.y, v.z, v.w,
                    sb + SM_X + (uint32_t)(ci * 136 + lr * 68 + qcol * 4) * 4);
        }
        if (tid < nr * 128) {                // zero halo cols 64,65
            int ci = tid & 63;
            int lr = (nr == 2) ? ((tid >> 6) & 1) : 0;
            int cz = 64 + ((nr == 2) ? (tid >> 7) : (tid >> 6));
            s_x[ci * 136 + lr * 68 + cz] = 0.0f;
        }
        __syncthreads();

        // convert fp32 -> fp16 + transpose -> B tile [fpix][ci] SW128
        const int npx    = nr * 66;
        const int citems = npx * 8;
        #pragma unroll 1
        for (int i = tid; i < citems; i += THREADS) {
            int pix = i % npx;
            int grp = i / npx;
            int lr  = (pix >= 66);
            int lc  = pix + 2 * lr;
            uint32_t hp[4];
            #pragma unroll
            for (int j = 0; j < 4; ++j) {
                __half h0 = __float2half_rn(s_x[((grp << 3) + 2 * j)     * 136 + lc]);
                __half h1 = __float2half_rn(s_x[((grp << 3) + 2 * j + 1) * 136 + lc]);
                hp[j] = (uint32_t)__half_as_ushort(h0) |
                        ((uint32_t)__half_as_ushort(h1) << 16);
            }
            uint32_t fpix = (uint32_t)(c2 * 132 + pix);
            uint32_t adr  = fpix * 128 +
                            (((uint32_t)grp * 16) ^ ((fpix & 7) << 4));
            STS128(hp[0], hp[1], hp[2], hp[3], sb + SM_B + adr);
        }
        __syncthreads();
    }

    // ===== main loop: 9 taps, single-pass fp16, A double-buffered =====
    #pragma unroll 1
    for (int kk = 0; kk < 9; ++kk) {
        CP_WAIT0();
        __syncthreads();
        if (kk < 8) {
            prefetch_A(kk + 1, sb + ((kk + 1) & 1 ? SM_A1 : SM_A0), tid);
            CP_COMMIT();
        }

        const uint32_t ab = sb + ((kk & 1) ? SM_A1 : SM_A0);
        const int ky = kk / 3, kx = kk - 3 * ky;
        const uint32_t lanepix =
            (uint32_t)((wn + ky) * 66 + kx + ((lid >> 4) & 1) * 8 + (lid & 7));
        const uint32_t b_base = sb + SM_B + lanepix * 128;
        const uint32_t b_xm2  = (lanepix & 7) << 4;

        #pragma unroll
        for (int ks = 0; ks < 4; ++ks) {
            const uint32_t aoff = ((uint32_t)(ks * 32) + a_kadd) ^ a_xm;
            const uint32_t boff = ((uint32_t)(ks * 32) + b_kadd) ^ b_xm2;

            uint32_t bh[16], ah[8];
            #pragma unroll
            for (int i2 = 0; i2 < 4; ++i2)
                ldm_x4(bh[i2 * 4 + 0], bh[i2 * 4 + 1], bh[i2 * 4 + 2], bh[i2 * 4 + 3],
                       b_base + (uint32_t)(i2 * 2048) + boff);
            #pragma unroll
            for (int m = 0; m < 2; ++m)
                ldm_x4(ah[m * 4 + 0], ah[m * 4 + 1], ah[m * 4 + 2], ah[m * 4 + 3],
                       ab + a_rb0 + (uint32_t)(m * 2048) + aoff);
            #pragma unroll
            for (int m = 0; m < 2; ++m)
                #pragma unroll
                for (int n = 0; n < 8; ++n)
                    mma_f16(acc[m][n], ah + m * 4, bh + (n >> 1) * 4 + (n & 1) * 2);
        }
    }

    // ===== epilogue: bias + store (row 62 of last tile skipped) =====
    const int oy = oy0 + wn;
    if (oy < OH) {
        #pragma unroll
        for (int m = 0; m < 2; ++m) {
            const int co0 = wm * 32 + m * 16 + (lid >> 2);
            const float bv0 = __ldg(&bias[co0]);
            const float bv1 = __ldg(&bias[co0 + 8]);
            float* op0 = out + ((size_t)(b * COut + co0)     * OH + oy) * OW;
            float* op1 = out + ((size_t)(b * COut + co0 + 8) * OH + oy) * OW;
            #pragma unroll
            for (int n = 0; n < 8; ++n) {
                const int col = n * 8 + (lid & 3) * 2;
                if (col < OW) {
                    float2 v0 = make_float2(acc[m][n][0] + bv0, acc[m][n][1] + bv0);
                    float2 v1 = make_float2(acc[m][n][2] + bv1, acc[m][n][3] + bv1);
                    *reinterpret_cast<float2*>(op0 + col) = v0;
                    *reinterpret_cast<float2*>(op1 + col) = v1;
                }
            }
        }
    }
}

} // namespace

extern "C" void kernel_launch(void* const* d_in, const int* in_sizes, int n_in,
                              void* d_out, int out_size) {
    const float* x    = nullptr;
    const float* wgt  = nullptr;
    const float* bias = nullptr;
    for (int i = 0; i < n_in; ++i) {
        const int sz = in_sizes[i];
        if (sz == BATCH * CIn * H * W) x    = (const float*)d_in[i];
        else if (sz == COut * CIn * 9) wgt  = (const float*)d_in[i];
        else if (sz == COut)           bias = (const float*)d_in[i];
    }
    if (!x)    x    = (const float*)d_in[0];
    if (!wgt)  wgt  = (const float*)d_in[1];
    if (!bias) bias = (const float*)d_in[2];
    float* out = (float*)d_out;
    (void)out_size;

    cudaFuncSetAttribute(conv_mma_kernel,
                         cudaFuncAttributeMaxDynamicSharedMemorySize, SM_TOTAL);

    wconv_kernel<<<(9 * 128 * 64 + 255) / 256, 256>>>(wgt);
    conv_mma_kernel<<<BATCH * TILES_PER_B, THREADS, SM_TOTAL>>>(x, bias, out);
}